// round 1
// baseline (speedup 1.0000x reference)
#include <cuda_runtime.h>
#include <cstdint>

// Compressor: per-8x8-block DCT-II (C = M^T B M), per-block inf-norm,
// int8 quantization with round-to-nearest-even.
//
// x: 8192x8192 fp32.  dct: 8x8 fp32, M[element][frequency].
// indices[b1][b2][g][h] int8 (64 contiguous bytes per block), biggest[b1][b2] fp32.

static constexpr int W_DIM  = 8192;
static constexpr int BLK    = 8;
static constexpr float RADIUS = 127.0f;

// OUT_FLOAT=false: d_out = [int8 indices (n bytes)][float biggest (nblocks floats)]
// OUT_FLOAT=true : d_out = [float indices (n floats)][float biggest (nblocks floats)]
template <bool OUT_FLOAT>
__global__ __launch_bounds__(256)
void dct_quant_kernel(const float* __restrict__ x,
                      const float* __restrict__ dct,
                      void* __restrict__ out_indices,
                      float* __restrict__ out_biggest,
                      int blocks_per_row)
{
    __shared__ float Ms[64];
    const int tid = threadIdx.x;
    if (tid < 64) Ms[tid] = dct[tid];
    __syncthreads();

    const int t  = blockIdx.x * blockDim.x + tid;
    const int b1 = t / blocks_per_row;
    const int b2 = t - b1 * blocks_per_row;

    // ---- Load 8x8 block, front-batched float4 loads (MLP ~16) ----
    const float* src = x + (size_t)(b1 * BLK) * W_DIM + (size_t)b2 * BLK;
    float B[8][8];
#pragma unroll
    for (int e = 0; e < 8; e++) {
        const float4 v0 = *reinterpret_cast<const float4*>(src + (size_t)e * W_DIM);
        const float4 v1 = *reinterpret_cast<const float4*>(src + (size_t)e * W_DIM + 4);
        B[e][0] = v0.x; B[e][1] = v0.y; B[e][2] = v0.z; B[e][3] = v0.w;
        B[e][4] = v1.x; B[e][5] = v1.y; B[e][6] = v1.z; B[e][7] = v1.w;
    }

    // ---- D = M^T B : D[g][f] = sum_e M[e][g] * B[e][f]  (B dies as D grows) ----
    float D[8][8];
#pragma unroll
    for (int g = 0; g < 8; g++)
#pragma unroll
        for (int f = 0; f < 8; f++) D[g][f] = 0.0f;
#pragma unroll
    for (int e = 0; e < 8; e++) {
#pragma unroll
        for (int g = 0; g < 8; g++) {
            const float m = Ms[e * 8 + g];
#pragma unroll
            for (int f = 0; f < 8; f++)
                D[g][f] = fmaf(m, B[e][f], D[g][f]);
        }
    }

    // ---- C = D M : C[g][h] = sum_f D[g][f] * M[f][h]  (D dies as C grows) ----
    float C[8][8];
    float maxv = 0.0f;
#pragma unroll
    for (int g = 0; g < 8; g++) {
        float acc[8];
#pragma unroll
        for (int h = 0; h < 8; h++) acc[h] = 0.0f;
#pragma unroll
        for (int f = 0; f < 8; f++) {
            const float d = D[g][f];
#pragma unroll
            for (int h = 0; h < 8; h++)
                acc[h] = fmaf(d, Ms[f * 8 + h], acc[h]);
        }
#pragma unroll
        for (int h = 0; h < 8; h++) {
            C[g][h] = acc[h];
            maxv = fmaxf(maxv, fabsf(acc[h]));
        }
    }

    const float scale = RADIUS / maxv;

    if (OUT_FLOAT) {
        // indices as float32 (concatenated-as-float layout)
        float* outp = reinterpret_cast<float*>(out_indices) + (size_t)t * 64;
#pragma unroll
        for (int g = 0; g < 8; g++) {
            float4 w0, w1;
            // round-half-even then int8 wrap semantics (values stay within [-127,127])
            w0.x = (float)__float2int_rn(C[g][0] * scale);
            w0.y = (float)__float2int_rn(C[g][1] * scale);
            w0.z = (float)__float2int_rn(C[g][2] * scale);
            w0.w = (float)__float2int_rn(C[g][3] * scale);
            w1.x = (float)__float2int_rn(C[g][4] * scale);
            w1.y = (float)__float2int_rn(C[g][5] * scale);
            w1.z = (float)__float2int_rn(C[g][6] * scale);
            w1.w = (float)__float2int_rn(C[g][7] * scale);
            reinterpret_cast<float4*>(outp + g * 8)[0] = w0;
            reinterpret_cast<float4*>(outp + g * 8)[1] = w1;
        }
    } else {
        // int8 indices: 64 contiguous bytes per block -> 4x 16B stores
        uint32_t words[16];
#pragma unroll
        for (int i = 0; i < 16; i++) {
            const int g = i >> 1;
            const int hb = (i & 1) * 4;
            uint32_t w = 0;
#pragma unroll
            for (int j = 0; j < 4; j++) {
                const int q = __float2int_rn(C[g][hb + j] * scale);
                w |= (uint32_t)(q & 0xFF) << (8 * j);
            }
            words[i] = w;
        }
        uint4* outp = reinterpret_cast<uint4*>(
            reinterpret_cast<int8_t*>(out_indices) + (size_t)t * 64);
#pragma unroll
        for (int i = 0; i < 4; i++)
            outp[i] = make_uint4(words[4*i], words[4*i+1], words[4*i+2], words[4*i+3]);
    }

    out_biggest[t] = maxv;
}

extern "C" void kernel_launch(void* const* d_in, const int* in_sizes, int n_in,
                              void* d_out, int out_size)
{
    const float* x   = (const float*)d_in[0];
    const float* dct = (const float*)d_in[1];

    const int n        = in_sizes[0];          // 67108864
    const int nblocks  = n / 64;               // 1048576
    const int bpr      = W_DIM / BLK;          // 1024 blocks per row
    const int threads  = 256;
    const int grid     = nblocks / threads;    // 4096

    if (out_size == n + nblocks) {
        // All-float32 concatenated layout: [indices as f32][biggest f32]
        float* outF = (float*)d_out;
        dct_quant_kernel<true><<<grid, threads>>>(x, dct, (void*)outF, outF + n, bpr);
    } else {
        // Byte-packed layout: [indices int8 (n bytes)][biggest f32]
        int8_t* idx = (int8_t*)d_out;
        float*  big = (float*)((char*)d_out + (size_t)n);
        dct_quant_kernel<false><<<grid, threads>>>(x, dct, (void*)idx, big, bpr);
    }
}